// round 12
// baseline (speedup 1.0000x reference)
#include <cuda_runtime.h>
#include <cuda_bf16.h>
#include <cuda_fp16.h>
#include <math.h>
#include <stdint.h>

#define NNODES 50000
#define NEDGES 800000
#define ETOT   (NEDGES + NNODES)   // reference appends one self-loop per node
#define DIM    256
#define HEADS  8

// ---------------- scratch (static device globals; no allocation) ----------------
__device__ __half g_xh16[(size_t)NNODES * DIM];  // x @ W (fp16, for gathers)
__device__ __half g_in[(size_t)NNODES * DIM];    // layer input (fp16, GEMM A operand)
__device__ float g_als[NNODES * HEADS];
__device__ float g_ald[NNODES * HEADS];
__device__ __half g_wt_hi[DIM * DIM];            // W^T split hi [n][k]
__device__ __half g_wt_lo[DIM * DIM];            // W^T split lo [n][k]
// CSR by dst
__device__ int g_deg[NNODES];
__device__ int g_cursor[NNODES];
__device__ int g_off[NNODES + 1];
__device__ int g_csr_src[ETOT];

// ---------------- CSR build ----------------
__global__ void csr_zero_kernel() {
    int i = blockIdx.x * blockDim.x + threadIdx.x;
    if (i < NNODES) { g_deg[i] = 0; g_cursor[i] = 0; }
}

__global__ void csr_count_kernel(const int* __restrict__ ei) {
    int e = blockIdx.x * blockDim.x + threadIdx.x;
    if (e >= ETOT) return;
    int d = (e < NEDGES) ? ei[NEDGES + e] : e - NEDGES;
    atomicAdd(&g_deg[d], 1);
}

__global__ void csr_scan_kernel() {
    __shared__ int partial[1024];
    int tid = threadIdx.x;
    const int CH = (NNODES + 1023) / 1024;
    int base = tid * CH;
    int s = 0;
    for (int i = 0; i < CH; i++) {
        int j = base + i;
        if (j < NNODES) s += g_deg[j];
    }
    partial[tid] = s;
    __syncthreads();
    for (int off = 1; off < 1024; off <<= 1) {
        int v = (tid >= off) ? partial[tid - off] : 0;
        __syncthreads();
        partial[tid] += v;
        __syncthreads();
    }
    int run = (tid == 0) ? 0 : partial[tid - 1];
    for (int i = 0; i < CH; i++) {
        int j = base + i;
        if (j < NNODES) {
            int c = g_deg[j];
            g_off[j] = run;
            run += c;
        }
    }
    if (tid == 0) g_off[NNODES] = ETOT;
}

__global__ void csr_scatter_kernel(const int* __restrict__ ei) {
    int e = blockIdx.x * blockDim.x + threadIdx.x;
    if (e >= ETOT) return;
    int s, d;
    if (e < NEDGES) { s = ei[e]; d = ei[NEDGES + e]; }
    else            { s = d = e - NEDGES; }
    int pos = g_off[d] + atomicAdd(&g_cursor[d], 1);
    g_csr_src[pos] = s;
}

// ---------------- splits ----------------
__global__ void wsplit_kernel(const float* __restrict__ W) {
    int idx = blockIdx.x * blockDim.x + threadIdx.x;  // 65536
    int k = idx >> 8, n = idx & 255;
    float v = W[k * DIM + n];
    __half hi = __float2half_rn(v);
    g_wt_hi[n * DIM + k] = hi;
    g_wt_lo[n * DIM + k] = __float2half_rn(v - __half2float(hi));
}

__global__ void xsplit_kernel(const float* __restrict__ x) {
    int idx = blockIdx.x * blockDim.x + threadIdx.x;   // per 4 elems
    if (idx >= NNODES * DIM / 4) return;
    float4 v = ((const float4*)x)[idx];
    __half2* H = (__half2*)g_in + idx * 2;
    H[0] = __floats2half2_rn(v.x, v.y);
    H[1] = __floats2half2_rn(v.z, v.w);
}

// ---- tensor-core GEMM: xh = A(fp16) @ (B_hi + B_lo)^T, fused logits epilogue ----
__device__ __forceinline__ void ldsm4(uint32_t* r, uint32_t addr) {
    asm volatile("ldmatrix.sync.aligned.m8n8.x4.shared.b16 {%0,%1,%2,%3}, [%4];"
                 : "=r"(r[0]), "=r"(r[1]), "=r"(r[2]), "=r"(r[3]) : "r"(addr));
}

__device__ __forceinline__ void mma16816(float* c, const uint32_t* a, const uint32_t* b) {
    asm volatile("mma.sync.aligned.m16n8k16.row.col.f32.f16.f16.f32 "
                 "{%0,%1,%2,%3}, {%4,%5,%6,%7}, {%8,%9}, {%0,%1,%2,%3};"
                 : "+f"(c[0]), "+f"(c[1]), "+f"(c[2]), "+f"(c[3])
                 : "r"(a[0]), "r"(a[1]), "r"(a[2]), "r"(a[3]), "r"(b[0]), "r"(b[1]));
}

#define CPA16(dst, src, n) \
    asm volatile("cp.async.cg.shared.global [%0], [%1], 16, %2;" \
                 :: "r"(dst), "l"(src), "r"(n))

// 2-stage double buffer; each stage holds A / Bhi / Blo tiles of 128x16 fp16
// (row pitch 48B -> conflict-free ldmatrix phases). Stage stride 18432 B.
#define TILE_B    6144
#define STAGE_B   18432
#define GEMM_SMEM (STAGE_B * 2)

__global__ __launch_bounds__(256) void mma_gemm_kernel(const float* __restrict__ a_src,
                                                       const float* __restrict__ a_dst) {
    extern __shared__ char smem[];
    uint32_t sb;
    asm("{ .reg .u64 t; cvta.to.shared.u64 t, %1; cvt.u32.u64 %0, t; }"
        : "=r"(sb) : "l"(smem));

    const int tid = threadIdx.x, lane = tid & 31, wid = tid >> 5;
    const int warpM = wid & 3, warpN = wid >> 2;
    const int bm = blockIdx.y, bn = blockIdx.x;

    // staging: thread -> one 16B chunk per tile per stage
    const int srow = tid >> 1, shalf = tid & 1;
    const uint32_t sdst = (uint32_t)(srow * 48 + shalf * 16);
    int grA = bm * 128 + srow;
    const uint32_t aok = (grA < NNODES) ? 16u : 0u;
    if (grA >= NNODES) grA = 0;   // keep address in-bounds; src-size=0 zero-fills
    const char* pA  = (const char*)(g_in + (size_t)grA * DIM + shalf * 8);
    const char* pBh = (const char*)(g_wt_hi + (size_t)(bn * 128 + srow) * DIM + shalf * 8);
    const char* pBl = (const char*)(g_wt_lo + (size_t)(bn * 128 + srow) * DIM + shalf * 8);

    float c[2][8][4];
#pragma unroll
    for (int i = 0; i < 2; i++)
#pragma unroll
        for (int j = 0; j < 8; j++)
#pragma unroll
            for (int q = 0; q < 4; q++) c[i][j][q] = 0.0f;

#define ISSUE(S, KB)                                                       \
    do {                                                                   \
        uint32_t st = sb + (S) * STAGE_B + sdst;                           \
        CPA16(st + 0 * TILE_B, pA  + (KB), aok);                           \
        CPA16(st + 1 * TILE_B, pBh + (KB), 16u);                           \
        CPA16(st + 2 * TILE_B, pBl + (KB), 16u);                           \
        asm volatile("cp.async.commit_group;" ::: "memory");               \
    } while (0)

    const uint32_t aoff = (uint32_t)((warpM * 32 + (lane & 15)) * 48 + ((lane >> 4) << 4));
    const uint32_t boff = (uint32_t)((warpN * 64 + ((lane >> 4) & 1) * 8 + (lane & 7)) * 48 +
                                     (((lane >> 3) & 1) << 4));

    ISSUE(0, 0);

    int buf = 0;
    for (int kc = 0; kc < 16; kc++) {
        asm volatile("cp.async.wait_group 0;" ::: "memory");  // stage kc landed
        __syncthreads();   // visibility + all reads of buf^1 (iter kc-1) finished
        if (kc < 15) ISSUE(buf ^ 1, (kc + 1) * 32);           // overlaps compute below

        const uint32_t stg = sb + buf * STAGE_B;
        uint32_t ah[2][4], bh[8][2], blr[8][2];
        ldsm4(ah[0], stg + 0 * TILE_B + aoff);
        ldsm4(ah[1], stg + 0 * TILE_B + aoff + 16 * 48);
#pragma unroll
        for (int p = 0; p < 4; p++) {
            ldsm4(&bh[2 * p][0], stg + 1 * TILE_B + boff + p * 16 * 48);
            ldsm4(&blr[2 * p][0], stg + 2 * TILE_B + boff + p * 16 * 48);
        }

#pragma unroll
        for (int tm = 0; tm < 2; tm++)
#pragma unroll
            for (int tn = 0; tn < 8; tn++) {
                mma16816(c[tm][tn], ah[tm], bh[tn]);   // A * B_hi
                mma16816(c[tm][tn], ah[tm], blr[tn]);  // A * B_lo
            }
        buf ^= 1;
    }

    // ---- epilogue: fp16 store + fused per-head logit partials ----
    // head h occupies cols [h*32, h*32+32) -> entirely inside this (bn, warpN)
    // 64-col group: head = bn*4 + warpN*2 + (tn>>2). Each thread covers 16 cols
    // of 4 rows; reduce partials over the 4 lanes sharing a row (lane&3).
    const int g = lane >> 2, cc = (lane & 3) * 2;
    float ps[2][2][2], pd[2][2][2];   // [tm][rowhalf][hh]
#pragma unroll
    for (int tm = 0; tm < 2; tm++)
#pragma unroll
        for (int rh = 0; rh < 2; rh++)
#pragma unroll
            for (int hh = 0; hh < 2; hh++) { ps[tm][rh][hh] = 0.f; pd[tm][rh][hh] = 0.f; }

#pragma unroll
    for (int tm = 0; tm < 2; tm++) {
        int r0 = bm * 128 + warpM * 32 + tm * 16 + g;
        int r1 = r0 + 8;
#pragma unroll
        for (int tn = 0; tn < 8; tn++) {
            int col = bn * 128 + warpN * 64 + tn * 8 + cc;
            float2 av = *(const float2*)&a_src[col];
            float2 dv = *(const float2*)&a_dst[col];
            int hh = tn >> 2;
            ps[tm][0][hh] += c[tm][tn][0] * av.x + c[tm][tn][1] * av.y;
            pd[tm][0][hh] += c[tm][tn][0] * dv.x + c[tm][tn][1] * dv.y;
            ps[tm][1][hh] += c[tm][tn][2] * av.x + c[tm][tn][3] * av.y;
            pd[tm][1][hh] += c[tm][tn][2] * dv.x + c[tm][tn][3] * dv.y;
            if (r0 < NNODES)
                *(__half2*)&g_xh16[(size_t)r0 * DIM + col] =
                    __floats2half2_rn(c[tm][tn][0], c[tm][tn][1]);
            if (r1 < NNODES)
                *(__half2*)&g_xh16[(size_t)r1 * DIM + col] =
                    __floats2half2_rn(c[tm][tn][2], c[tm][tn][3]);
        }
    }

    // reduce over the 4 lanes that share each row (lane&3 = 0..3)
#pragma unroll
    for (int tm = 0; tm < 2; tm++)
#pragma unroll
        for (int rh = 0; rh < 2; rh++)
#pragma unroll
            for (int hh = 0; hh < 2; hh++) {
                float vs = ps[tm][rh][hh], vd = pd[tm][rh][hh];
                vs += __shfl_xor_sync(0xffffffffu, vs, 1);
                vs += __shfl_xor_sync(0xffffffffu, vs, 2);
                vd += __shfl_xor_sync(0xffffffffu, vd, 1);
                vd += __shfl_xor_sync(0xffffffffu, vd, 2);
                ps[tm][rh][hh] = vs;
                pd[tm][rh][hh] = vd;
            }

    if ((lane & 3) == 0) {
        int headbase = bn * 4 + warpN * 2;
#pragma unroll
        for (int tm = 0; tm < 2; tm++)
#pragma unroll
            for (int rh = 0; rh < 2; rh++) {
                int r = bm * 128 + warpM * 32 + tm * 16 + g + rh * 8;
                if (r < NNODES) {
#pragma unroll
                    for (int hh = 0; hh < 2; hh++) {
                        g_als[r * HEADS + headbase + hh] = ps[tm][rh][hh];
                        g_ald[r * HEADS + headbase + hh] = pd[tm][rh][hh];
                    }
                }
            }
    }
#undef ISSUE
}

// ---------------- fused online-softmax aggregation (CSR), 4-edge unrolled --------
// one warp per dst node; lane l handles channels [8l,8l+8), head = l>>2
// gathers fp16 mirror; layers 0-2 write ELU(out) as fp16 (next GEMM A operand)
__global__ void aggr_fused_kernel(const float* __restrict__ bvec,
                                  float* __restrict__ out, int apply_elu) {
    int warp = (blockIdx.x * blockDim.x + threadIdx.x) >> 5;
    int lane = threadIdx.x & 31;
    if (warp >= NNODES) return;

    int beg = g_off[warp], end = g_off[warp + 1];
    int h = lane >> 2;
    float aldh = g_ald[warp * HEADS + h];

    float m = -INFINITY, denom = 0.0f;
    float acc[8];
#pragma unroll
    for (int j = 0; j < 8; j++) acc[j] = 0.0f;

    int i = beg;
    for (; i + 4 <= end; i += 4) {
        int s0 = g_csr_src[i + 0];
        int s1 = g_csr_src[i + 1];
        int s2 = g_csr_src[i + 2];
        int s3 = g_csr_src[i + 3];
        // issue all 4 gathers + 4 logit loads before any dependent math (MLP=4);
        // raws stay packed in uint4 until weights are ready (low reg pressure)
        uint4 raw0 = *(const uint4*)(g_xh16 + (size_t)s0 * DIM + lane * 8);
        uint4 raw1 = *(const uint4*)(g_xh16 + (size_t)s1 * DIM + lane * 8);
        uint4 raw2 = *(const uint4*)(g_xh16 + (size_t)s2 * DIM + lane * 8);
        uint4 raw3 = *(const uint4*)(g_xh16 + (size_t)s3 * DIM + lane * 8);
        float e0 = g_als[s0 * HEADS + h];
        float e1 = g_als[s1 * HEADS + h];
        float e2 = g_als[s2 * HEADS + h];
        float e3 = g_als[s3 * HEADS + h];

        e0 += aldh; e0 = e0 > 0.0f ? e0 : 0.2f * e0;
        e1 += aldh; e1 = e1 > 0.0f ? e1 : 0.2f * e1;
        e2 += aldh; e2 = e2 > 0.0f ? e2 : 0.2f * e2;
        e3 += aldh; e3 = e3 > 0.0f ? e3 : 0.2f * e3;

        float mn = fmaxf(fmaxf(m, fmaxf(e0, e1)), fmaxf(e2, e3));
        float r  = __expf(m - mn);          // m=-inf first time -> r=0
        float a0 = __expf(e0 - mn);
        float a1 = __expf(e1 - mn);
        float a2 = __expf(e2 - mn);
        float a3 = __expf(e3 - mn);
        denom = denom * r + a0 + a1 + a2 + a3;
        m = mn;

#pragma unroll
        for (int q = 0; q < 4; q++) {
            float2 u = __half22float2(((const __half2*)&raw0)[q]);
            float2 w = __half22float2(((const __half2*)&raw1)[q]);
            float2 y = __half22float2(((const __half2*)&raw2)[q]);
            float2 z = __half22float2(((const __half2*)&raw3)[q]);
            acc[2 * q + 0] = acc[2 * q + 0] * r + a0 * u.x + a1 * w.x + a2 * y.x + a3 * z.x;
            acc[2 * q + 1] = acc[2 * q + 1] * r + a0 * u.y + a1 * w.y + a2 * y.y + a3 * z.y;
        }
    }
    for (; i < end; i++) {
        int s = g_csr_src[i];
        uint4 raw = *(const uint4*)(g_xh16 + (size_t)s * DIM + lane * 8);
        float e = g_als[s * HEADS + h] + aldh;
        e = e > 0.0f ? e : 0.2f * e;
        float mn = fmaxf(m, e);
        float r = __expf(m - mn);
        float a = __expf(e - mn);
        denom = denom * r + a;
        m = mn;
#pragma unroll
        for (int q = 0; q < 4; q++) {
            float2 u = __half22float2(((const __half2*)&raw)[q]);
            acc[2 * q + 0] = acc[2 * q + 0] * r + a * u.x;
            acc[2 * q + 1] = acc[2 * q + 1] * r + a * u.y;
        }
    }

    float inv = 1.0f / denom;
    const float* bb = bvec + lane * 8;
    float v[8];
#pragma unroll
    for (int j = 0; j < 8; j++) v[j] = acc[j] * inv + bb[j];

    if (apply_elu) {
        __half2 o2[4];
#pragma unroll
        for (int j = 0; j < 8; j += 2) {
            float v0 = v[j] > 0.0f ? v[j] : expm1f(v[j]);
            float v1 = v[j + 1] > 0.0f ? v[j + 1] : expm1f(v[j + 1]);
            o2[j >> 1] = __floats2half2_rn(v0, v1);
        }
        *(uint4*)(g_in + (size_t)warp * DIM + lane * 8) = *(uint4*)o2;
    } else {
        float* o = out + (size_t)warp * DIM + lane * 8;
        *(float4*)(o + 0) = make_float4(v[0], v[1], v[2], v[3]);
        *(float4*)(o + 4) = make_float4(v[4], v[5], v[6], v[7]);
    }
}

// ---------------- host launcher ----------------
extern "C" void kernel_launch(void* const* d_in, const int* in_sizes, int n_in,
                              void* d_out, int out_size) {
    const float* x  = (const float*)d_in[0];
    const int*   ei = (const int*)d_in[1];
    float* out = (float*)d_out;

    cudaFuncSetAttribute(mma_gemm_kernel,
                         cudaFuncAttributeMaxDynamicSharedMemorySize, GEMM_SMEM);

    const int TPB = 256;
    dim3 gemm_grid(DIM / 128, (NNODES + 127) / 128);
    int node_blocks = (NNODES + TPB - 1) / TPB;
    int edge_blocks = (ETOT + TPB - 1) / TPB;
    int warp_blocks = (NNODES * 32 + TPB - 1) / TPB;
    int wsplit_blocks = (DIM * DIM) / TPB;
    int xsplit_blocks = (NNODES * DIM / 4 + TPB - 1) / TPB;

    // build CSR once (same graph for all 4 layers)
    csr_zero_kernel<<<node_blocks, TPB>>>();
    csr_count_kernel<<<edge_blocks, TPB>>>(ei);
    csr_scan_kernel<<<1, 1024>>>();
    csr_scatter_kernel<<<edge_blocks, TPB>>>(ei);

    xsplit_kernel<<<xsplit_blocks, TPB>>>(x);

    for (int layer = 0; layer < 4; layer++) {
        const float* W   = (const float*)d_in[2 + 4 * layer];
        const float* as_ = (const float*)d_in[3 + 4 * layer];
        const float* ad_ = (const float*)d_in[4 + 4 * layer];
        const float* b   = (const float*)d_in[5 + 4 * layer];

        wsplit_kernel<<<wsplit_blocks, TPB>>>(W);
        mma_gemm_kernel<<<gemm_grid, TPB, GEMM_SMEM>>>(as_, ad_);

        aggr_fused_kernel<<<warp_blocks, TPB>>>(b, (layer < 3) ? nullptr : out,
                                                layer < 3 ? 1 : 0);
    }
}

// round 13
// speedup vs baseline: 1.0288x; 1.0288x over previous
#include <cuda_runtime.h>
#include <cuda_bf16.h>
#include <cuda_fp16.h>
#include <math.h>
#include <stdint.h>

#define NNODES 50000
#define NEDGES 800000
#define ETOT   (NEDGES + NNODES)   // reference appends one self-loop per node
#define DIM    256
#define HEADS  8

// ---------------- scratch (static device globals; no allocation) ----------------
__device__ __half g_xh16[(size_t)NNODES * DIM];  // x @ W (fp16, for gathers)
__device__ __half g_in[(size_t)NNODES * DIM];    // layer input (fp16, GEMM A operand)
__device__ float g_als[NNODES * HEADS];
__device__ float g_ald[NNODES * HEADS];
__device__ __half g_wt_hi[4][DIM * DIM];         // per-layer W^T split hi [n][k]
__device__ __half g_wt_lo[4][DIM * DIM];         // per-layer W^T split lo [n][k]
// CSR by dst
__device__ int g_deg[NNODES];
__device__ int g_cursor[NNODES];
__device__ int g_off[NNODES + 1];
__device__ int g_csr_src[ETOT];

// ---------------- CSR build ----------------
__global__ void csr_zero_kernel() {
    int i = blockIdx.x * blockDim.x + threadIdx.x;
    if (i < NNODES) { g_deg[i] = 0; g_cursor[i] = 0; }
}

__global__ void csr_count_kernel(const int* __restrict__ ei) {
    int e = blockIdx.x * blockDim.x + threadIdx.x;
    if (e >= ETOT) return;
    int d = (e < NEDGES) ? ei[NEDGES + e] : e - NEDGES;
    atomicAdd(&g_deg[d], 1);
}

__global__ void csr_scan_kernel() {
    __shared__ int partial[1024];
    int tid = threadIdx.x;
    const int CH = (NNODES + 1023) / 1024;
    int base = tid * CH;
    int s = 0;
    for (int i = 0; i < CH; i++) {
        int j = base + i;
        if (j < NNODES) s += g_deg[j];
    }
    partial[tid] = s;
    __syncthreads();
    for (int off = 1; off < 1024; off <<= 1) {
        int v = (tid >= off) ? partial[tid - off] : 0;
        __syncthreads();
        partial[tid] += v;
        __syncthreads();
    }
    int run = (tid == 0) ? 0 : partial[tid - 1];
    for (int i = 0; i < CH; i++) {
        int j = base + i;
        if (j < NNODES) {
            int c = g_deg[j];
            g_off[j] = run;
            run += c;
        }
    }
    if (tid == 0) g_off[NNODES] = ETOT;
}

__global__ void csr_scatter_kernel(const int* __restrict__ ei) {
    int e = blockIdx.x * blockDim.x + threadIdx.x;
    if (e >= ETOT) return;
    int s, d;
    if (e < NEDGES) { s = ei[e]; d = ei[NEDGES + e]; }
    else            { s = d = e - NEDGES; }
    int pos = g_off[d] + atomicAdd(&g_cursor[d], 1);
    g_csr_src[pos] = s;
}

// ---------------- splits ----------------
// all 4 layers' W split upfront (weights don't depend on layer outputs)
__global__ void wsplit_all_kernel(const float* __restrict__ W0,
                                  const float* __restrict__ W1,
                                  const float* __restrict__ W2,
                                  const float* __restrict__ W3) {
    int idx = blockIdx.x * blockDim.x + threadIdx.x;  // 4 * 65536
    int layer = idx >> 16;
    int r = idx & 65535;
    int k = r >> 8, n = r & 255;
    const float* W = (layer == 0) ? W0 : (layer == 1) ? W1 : (layer == 2) ? W2 : W3;
    float v = W[k * DIM + n];
    __half hi = __float2half_rn(v);
    g_wt_hi[layer][n * DIM + k] = hi;
    g_wt_lo[layer][n * DIM + k] = __float2half_rn(v - __half2float(hi));
}

__global__ void xsplit_kernel(const float* __restrict__ x) {
    int idx = blockIdx.x * blockDim.x + threadIdx.x;   // per 4 elems
    if (idx >= NNODES * DIM / 4) return;
    float4 v = ((const float4*)x)[idx];
    __half2* H = (__half2*)g_in + idx * 2;
    H[0] = __floats2half2_rn(v.x, v.y);
    H[1] = __floats2half2_rn(v.z, v.w);
}

// ---- tensor-core GEMM: xh = A(fp16) @ (B_hi + B_lo)^T, fused logits epilogue ----
__device__ __forceinline__ void ldsm4(uint32_t* r, uint32_t addr) {
    asm volatile("ldmatrix.sync.aligned.m8n8.x4.shared.b16 {%0,%1,%2,%3}, [%4];"
                 : "=r"(r[0]), "=r"(r[1]), "=r"(r[2]), "=r"(r[3]) : "r"(addr));
}

__device__ __forceinline__ void mma16816(float* c, const uint32_t* a, const uint32_t* b) {
    asm volatile("mma.sync.aligned.m16n8k16.row.col.f32.f16.f16.f32 "
                 "{%0,%1,%2,%3}, {%4,%5,%6,%7}, {%8,%9}, {%0,%1,%2,%3};"
                 : "+f"(c[0]), "+f"(c[1]), "+f"(c[2]), "+f"(c[3])
                 : "r"(a[0]), "r"(a[1]), "r"(a[2]), "r"(a[3]), "r"(b[0]), "r"(b[1]));
}

#define CPA16(dst, src, n) \
    asm volatile("cp.async.cg.shared.global [%0], [%1], 16, %2;" \
                 :: "r"(dst), "l"(src), "r"(n))

// 2-stage double buffer; each stage holds A / Bhi / Blo tiles of 128x16 fp16
// (row pitch 48B -> conflict-free ldmatrix phases). Stage stride 18432 B.
#define TILE_B    6144
#define STAGE_B   18432
#define GEMM_SMEM (STAGE_B * 2)

__global__ __launch_bounds__(256) void mma_gemm_kernel(const float* __restrict__ a_src,
                                                       const float* __restrict__ a_dst,
                                                       int layer) {
    extern __shared__ char smem[];
    uint32_t sb;
    asm("{ .reg .u64 t; cvta.to.shared.u64 t, %1; cvt.u32.u64 %0, t; }"
        : "=r"(sb) : "l"(smem));

    const int tid = threadIdx.x, lane = tid & 31, wid = tid >> 5;
    const int warpM = wid & 3, warpN = wid >> 2;
    const int bm = blockIdx.y, bn = blockIdx.x;

    // staging: thread -> one 16B chunk per tile per stage
    const int srow = tid >> 1, shalf = tid & 1;
    const uint32_t sdst = (uint32_t)(srow * 48 + shalf * 16);
    int grA = bm * 128 + srow;
    const uint32_t aok = (grA < NNODES) ? 16u : 0u;
    if (grA >= NNODES) grA = 0;   // keep address in-bounds; src-size=0 zero-fills
    const char* pA  = (const char*)(g_in + (size_t)grA * DIM + shalf * 8);
    const char* pBh = (const char*)(&g_wt_hi[layer][(size_t)(bn * 128 + srow) * DIM] + shalf * 8);
    const char* pBl = (const char*)(&g_wt_lo[layer][(size_t)(bn * 128 + srow) * DIM] + shalf * 8);

    float c[2][8][4];
#pragma unroll
    for (int i = 0; i < 2; i++)
#pragma unroll
        for (int j = 0; j < 8; j++)
#pragma unroll
            for (int q = 0; q < 4; q++) c[i][j][q] = 0.0f;

#define ISSUE(S, KB)                                                       \
    do {                                                                   \
        uint32_t st = sb + (S) * STAGE_B + sdst;                           \
        CPA16(st + 0 * TILE_B, pA  + (KB), aok);                           \
        CPA16(st + 1 * TILE_B, pBh + (KB), 16u);                           \
        CPA16(st + 2 * TILE_B, pBl + (KB), 16u);                           \
        asm volatile("cp.async.commit_group;" ::: "memory");               \
    } while (0)

    const uint32_t aoff = (uint32_t)((warpM * 32 + (lane & 15)) * 48 + ((lane >> 4) << 4));
    const uint32_t boff = (uint32_t)((warpN * 64 + ((lane >> 4) & 1) * 8 + (lane & 7)) * 48 +
                                     (((lane >> 3) & 1) << 4));

    ISSUE(0, 0);

    int buf = 0;
    for (int kc = 0; kc < 16; kc++) {
        asm volatile("cp.async.wait_group 0;" ::: "memory");  // stage kc landed
        __syncthreads();   // visibility + all reads of buf^1 (iter kc-1) finished
        if (kc < 15) ISSUE(buf ^ 1, (kc + 1) * 32);           // overlaps compute below

        const uint32_t stg = sb + buf * STAGE_B;
        uint32_t ah[2][4], bh[8][2], blr[8][2];
        ldsm4(ah[0], stg + 0 * TILE_B + aoff);
        ldsm4(ah[1], stg + 0 * TILE_B + aoff + 16 * 48);
#pragma unroll
        for (int p = 0; p < 4; p++) {
            ldsm4(&bh[2 * p][0], stg + 1 * TILE_B + boff + p * 16 * 48);
            ldsm4(&blr[2 * p][0], stg + 2 * TILE_B + boff + p * 16 * 48);
        }

#pragma unroll
        for (int tm = 0; tm < 2; tm++)
#pragma unroll
            for (int tn = 0; tn < 8; tn++) {
                mma16816(c[tm][tn], ah[tm], bh[tn]);   // A * B_hi
                mma16816(c[tm][tn], ah[tm], blr[tn]);  // A * B_lo
            }
        buf ^= 1;
    }

    // ---- epilogue: fp16 store + fused per-head logit partials ----
    // head h occupies cols [h*32, h*32+32) -> entirely inside this (bn, warpN)
    // 64-col group: head = bn*4 + warpN*2 + (tn>>2). Each thread covers 16 cols
    // of 4 rows; reduce partials over the 4 lanes sharing a row (lane&3).
    const int g = lane >> 2, cc = (lane & 3) * 2;
    float ps[2][2][2], pd[2][2][2];   // [tm][rowhalf][hh]
#pragma unroll
    for (int tm = 0; tm < 2; tm++)
#pragma unroll
        for (int rh = 0; rh < 2; rh++)
#pragma unroll
            for (int hh = 0; hh < 2; hh++) { ps[tm][rh][hh] = 0.f; pd[tm][rh][hh] = 0.f; }

#pragma unroll
    for (int tm = 0; tm < 2; tm++) {
        int r0 = bm * 128 + warpM * 32 + tm * 16 + g;
        int r1 = r0 + 8;
#pragma unroll
        for (int tn = 0; tn < 8; tn++) {
            int col = bn * 128 + warpN * 64 + tn * 8 + cc;
            float2 av = *(const float2*)&a_src[col];
            float2 dv = *(const float2*)&a_dst[col];
            int hh = tn >> 2;
            ps[tm][0][hh] += c[tm][tn][0] * av.x + c[tm][tn][1] * av.y;
            pd[tm][0][hh] += c[tm][tn][0] * dv.x + c[tm][tn][1] * dv.y;
            ps[tm][1][hh] += c[tm][tn][2] * av.x + c[tm][tn][3] * av.y;
            pd[tm][1][hh] += c[tm][tn][2] * dv.x + c[tm][tn][3] * dv.y;
            if (r0 < NNODES)
                *(__half2*)&g_xh16[(size_t)r0 * DIM + col] =
                    __floats2half2_rn(c[tm][tn][0], c[tm][tn][1]);
            if (r1 < NNODES)
                *(__half2*)&g_xh16[(size_t)r1 * DIM + col] =
                    __floats2half2_rn(c[tm][tn][2], c[tm][tn][3]);
        }
    }

    // reduce over the 4 lanes that share each row (lane&3 = 0..3)
#pragma unroll
    for (int tm = 0; tm < 2; tm++)
#pragma unroll
        for (int rh = 0; rh < 2; rh++)
#pragma unroll
            for (int hh = 0; hh < 2; hh++) {
                float vs = ps[tm][rh][hh], vd = pd[tm][rh][hh];
                vs += __shfl_xor_sync(0xffffffffu, vs, 1);
                vs += __shfl_xor_sync(0xffffffffu, vs, 2);
                vd += __shfl_xor_sync(0xffffffffu, vd, 1);
                vd += __shfl_xor_sync(0xffffffffu, vd, 2);
                ps[tm][rh][hh] = vs;
                pd[tm][rh][hh] = vd;
            }

    if ((lane & 3) == 0) {
        int headbase = bn * 4 + warpN * 2;
#pragma unroll
        for (int tm = 0; tm < 2; tm++)
#pragma unroll
            for (int rh = 0; rh < 2; rh++) {
                int r = bm * 128 + warpM * 32 + tm * 16 + g + rh * 8;
                if (r < NNODES) {
#pragma unroll
                    for (int hh = 0; hh < 2; hh++) {
                        g_als[r * HEADS + headbase + hh] = ps[tm][rh][hh];
                        g_ald[r * HEADS + headbase + hh] = pd[tm][rh][hh];
                    }
                }
            }
    }
#undef ISSUE
}

// ---------------- fused online-softmax aggregation (CSR), 2-edge unrolled --------
// one warp per dst node; lane l handles channels [8l,8l+8), head = l>>2
// gathers fp16 mirror; layers 0-2 write ELU(out) as fp16 (next GEMM A operand)
// 128-thread blocks: finer retirement granularity vs per-node degree variance
__global__ __launch_bounds__(128) void aggr_fused_kernel(const float* __restrict__ bvec,
                                                         float* __restrict__ out,
                                                         int apply_elu) {
    int warp = (blockIdx.x * blockDim.x + threadIdx.x) >> 5;
    int lane = threadIdx.x & 31;
    if (warp >= NNODES) return;

    int beg = g_off[warp], end = g_off[warp + 1];
    int h = lane >> 2;
    float aldh = g_ald[warp * HEADS + h];

    float m = -INFINITY, denom = 0.0f;
    float acc[8];
#pragma unroll
    for (int j = 0; j < 8; j++) acc[j] = 0.0f;

    int i = beg;
    for (; i + 2 <= end; i += 2) {
        int s0 = g_csr_src[i];
        int s1 = g_csr_src[i + 1];
        // issue both gathers + both logit loads before any dependent math (MLP=2)
        uint4 raw0 = *(const uint4*)(g_xh16 + (size_t)s0 * DIM + lane * 8);
        uint4 raw1 = *(const uint4*)(g_xh16 + (size_t)s1 * DIM + lane * 8);
        float e0 = g_als[s0 * HEADS + h];
        float e1 = g_als[s1 * HEADS + h];

        e0 += aldh; e0 = e0 > 0.0f ? e0 : 0.2f * e0;
        e1 += aldh; e1 = e1 > 0.0f ? e1 : 0.2f * e1;

        float mn = fmaxf(m, fmaxf(e0, e1));
        float r  = __expf(m - mn);          // m=-inf first time -> r=0
        float a0 = __expf(e0 - mn);
        float a1 = __expf(e1 - mn);
        denom = denom * r + a0 + a1;
        m = mn;

        float2 u0 = __half22float2(*(__half2*)&raw0.x);
        float2 u1 = __half22float2(*(__half2*)&raw0.y);
        float2 u2 = __half22float2(*(__half2*)&raw0.z);
        float2 u3 = __half22float2(*(__half2*)&raw0.w);
        float2 w0 = __half22float2(*(__half2*)&raw1.x);
        float2 w1 = __half22float2(*(__half2*)&raw1.y);
        float2 w2 = __half22float2(*(__half2*)&raw1.z);
        float2 w3 = __half22float2(*(__half2*)&raw1.w);

        acc[0] = acc[0] * r + a0 * u0.x + a1 * w0.x;
        acc[1] = acc[1] * r + a0 * u0.y + a1 * w0.y;
        acc[2] = acc[2] * r + a0 * u1.x + a1 * w1.x;
        acc[3] = acc[3] * r + a0 * u1.y + a1 * w1.y;
        acc[4] = acc[4] * r + a0 * u2.x + a1 * w2.x;
        acc[5] = acc[5] * r + a0 * u2.y + a1 * w2.y;
        acc[6] = acc[6] * r + a0 * u3.x + a1 * w3.x;
        acc[7] = acc[7] * r + a0 * u3.y + a1 * w3.y;
    }
    if (i < end) {
        int s = g_csr_src[i];
        uint4 raw = *(const uint4*)(g_xh16 + (size_t)s * DIM + lane * 8);
        float e = g_als[s * HEADS + h] + aldh;
        e = e > 0.0f ? e : 0.2f * e;
        float mn = fmaxf(m, e);
        float r = __expf(m - mn);
        float a = __expf(e - mn);
        denom = denom * r + a;
        m = mn;
        float2 u0 = __half22float2(*(__half2*)&raw.x);
        float2 u1 = __half22float2(*(__half2*)&raw.y);
        float2 u2 = __half22float2(*(__half2*)&raw.z);
        float2 u3 = __half22float2(*(__half2*)&raw.w);
        acc[0] = acc[0] * r + a * u0.x;
        acc[1] = acc[1] * r + a * u0.y;
        acc[2] = acc[2] * r + a * u1.x;
        acc[3] = acc[3] * r + a * u1.y;
        acc[4] = acc[4] * r + a * u2.x;
        acc[5] = acc[5] * r + a * u2.y;
        acc[6] = acc[6] * r + a * u3.x;
        acc[7] = acc[7] * r + a * u3.y;
    }

    float inv = 1.0f / denom;
    const float* bb = bvec + lane * 8;
    float v[8];
#pragma unroll
    for (int j = 0; j < 8; j++) v[j] = acc[j] * inv + bb[j];

    if (apply_elu) {
        __half2 o2[4];
#pragma unroll
        for (int j = 0; j < 8; j += 2) {
            float v0 = v[j] > 0.0f ? v[j] : expm1f(v[j]);
            float v1 = v[j + 1] > 0.0f ? v[j + 1] : expm1f(v[j + 1]);
            o2[j >> 1] = __floats2half2_rn(v0, v1);
        }
        *(uint4*)(g_in + (size_t)warp * DIM + lane * 8) = *(uint4*)o2;
    } else {
        float* o = out + (size_t)warp * DIM + lane * 8;
        *(float4*)(o + 0) = make_float4(v[0], v[1], v[2], v[3]);
        *(float4*)(o + 4) = make_float4(v[4], v[5], v[6], v[7]);
    }
}

// ---------------- host launcher ----------------
extern "C" void kernel_launch(void* const* d_in, const int* in_sizes, int n_in,
                              void* d_out, int out_size) {
    const float* x  = (const float*)d_in[0];
    const int*   ei = (const int*)d_in[1];
    float* out = (float*)d_out;

    cudaFuncSetAttribute(mma_gemm_kernel,
                         cudaFuncAttributeMaxDynamicSharedMemorySize, GEMM_SMEM);

    const int TPB = 256;
    dim3 gemm_grid(DIM / 128, (NNODES + 127) / 128);
    int node_blocks = (NNODES + TPB - 1) / TPB;
    int edge_blocks = (ETOT + TPB - 1) / TPB;
    int aggr_blocks = (NNODES * 32 + 127) / 128;     // 128-thread blocks
    int wsplit_blocks = (4 * DIM * DIM) / TPB;
    int xsplit_blocks = (NNODES * DIM / 4 + TPB - 1) / TPB;

    // build CSR once (same graph for all 4 layers); split all weights upfront
    csr_zero_kernel<<<node_blocks, TPB>>>();
    csr_count_kernel<<<edge_blocks, TPB>>>(ei);
    csr_scan_kernel<<<1, 1024>>>();
    csr_scatter_kernel<<<edge_blocks, TPB>>>(ei);

    wsplit_all_kernel<<<wsplit_blocks, TPB>>>((const float*)d_in[2], (const float*)d_in[6],
                                              (const float*)d_in[10], (const float*)d_in[14]);
    xsplit_kernel<<<xsplit_blocks, TPB>>>(x);

    for (int layer = 0; layer < 4; layer++) {
        const float* as_ = (const float*)d_in[3 + 4 * layer];
        const float* ad_ = (const float*)d_in[4 + 4 * layer];
        const float* b   = (const float*)d_in[5 + 4 * layer];

        mma_gemm_kernel<<<gemm_grid, TPB, GEMM_SMEM>>>(as_, ad_, layer);
        aggr_fused_kernel<<<aggr_blocks, 128>>>(b, (layer < 3) ? nullptr : out,
                                                layer < 3 ? 1 : 0);
    }
}

// round 14
// speedup vs baseline: 1.1324x; 1.1008x over previous
#include <cuda_runtime.h>
#include <cuda_bf16.h>
#include <cuda_fp16.h>
#include <math.h>
#include <stdint.h>

#define NNODES 50000
#define NEDGES 800000
#define ETOT   (NEDGES + NNODES)   // reference appends one self-loop per node
#define DIM    256
#define HEADS  8

// ---------------- scratch (static device globals; no allocation) ----------------
__device__ __half g_xh16[(size_t)NNODES * DIM];  // x @ W (fp16, for gathers)
__device__ __half g_in[(size_t)NNODES * DIM];    // layer input (fp16, GEMM A operand)
__device__ float g_als[NNODES * HEADS];
__device__ float g_ald[NNODES * HEADS];
__device__ __half g_wt_hi[4][DIM * DIM];         // per-layer W^T split hi [n][k]
__device__ __half g_wt_lo[4][DIM * DIM];         // per-layer W^T split lo [n][k]
// CSR by dst
__device__ int g_deg[NNODES];
__device__ int g_cursor[NNODES];
__device__ int g_off[NNODES + 1];
__device__ int g_csr_src[ETOT];

// ---------------- CSR build ----------------
__global__ void csr_zero_kernel() {
    int i = blockIdx.x * blockDim.x + threadIdx.x;
    if (i < NNODES) { g_deg[i] = 0; g_cursor[i] = 0; }
}

__global__ void csr_count_kernel(const int* __restrict__ ei) {
    int e = blockIdx.x * blockDim.x + threadIdx.x;
    if (e >= ETOT) return;
    int d = (e < NEDGES) ? ei[NEDGES + e] : e - NEDGES;
    atomicAdd(&g_deg[d], 1);
}

__global__ void csr_scan_kernel() {
    __shared__ int partial[1024];
    int tid = threadIdx.x;
    const int CH = (NNODES + 1023) / 1024;
    int base = tid * CH;
    int s = 0;
    for (int i = 0; i < CH; i++) {
        int j = base + i;
        if (j < NNODES) s += g_deg[j];
    }
    partial[tid] = s;
    __syncthreads();
    for (int off = 1; off < 1024; off <<= 1) {
        int v = (tid >= off) ? partial[tid - off] : 0;
        __syncthreads();
        partial[tid] += v;
        __syncthreads();
    }
    int run = (tid == 0) ? 0 : partial[tid - 1];
    for (int i = 0; i < CH; i++) {
        int j = base + i;
        if (j < NNODES) {
            int c = g_deg[j];
            g_off[j] = run;
            run += c;
        }
    }
    if (tid == 0) g_off[NNODES] = ETOT;
}

__global__ void csr_scatter_kernel(const int* __restrict__ ei) {
    int e = blockIdx.x * blockDim.x + threadIdx.x;
    if (e >= ETOT) return;
    int s, d;
    if (e < NEDGES) { s = ei[e]; d = ei[NEDGES + e]; }
    else            { s = d = e - NEDGES; }
    int pos = g_off[d] + atomicAdd(&g_cursor[d], 1);
    g_csr_src[pos] = s;
}

// ---------------- splits ----------------
// all 4 layers' W split upfront (weights don't depend on layer outputs)
__global__ void wsplit_all_kernel(const float* __restrict__ W0,
                                  const float* __restrict__ W1,
                                  const float* __restrict__ W2,
                                  const float* __restrict__ W3) {
    int idx = blockIdx.x * blockDim.x + threadIdx.x;  // 4 * 65536
    int layer = idx >> 16;
    int r = idx & 65535;
    int k = r >> 8, n = r & 255;
    const float* W = (layer == 0) ? W0 : (layer == 1) ? W1 : (layer == 2) ? W2 : W3;
    float v = W[k * DIM + n];
    __half hi = __float2half_rn(v);
    g_wt_hi[layer][n * DIM + k] = hi;
    g_wt_lo[layer][n * DIM + k] = __float2half_rn(v - __half2float(hi));
}

__global__ void xsplit_kernel(const float* __restrict__ x) {
    int idx = blockIdx.x * blockDim.x + threadIdx.x;   // per 4 elems
    if (idx >= NNODES * DIM / 4) return;
    float4 v = ((const float4*)x)[idx];
    __half2* H = (__half2*)g_in + idx * 2;
    H[0] = __floats2half2_rn(v.x, v.y);
    H[1] = __floats2half2_rn(v.z, v.w);
}

// ---- tensor-core GEMM: xh = A(fp16) @ (B_hi + B_lo)^T, fused logits epilogue ----
__device__ __forceinline__ void ldsm4(uint32_t* r, uint32_t addr) {
    asm volatile("ldmatrix.sync.aligned.m8n8.x4.shared.b16 {%0,%1,%2,%3}, [%4];"
                 : "=r"(r[0]), "=r"(r[1]), "=r"(r[2]), "=r"(r[3]) : "r"(addr));
}

__device__ __forceinline__ void mma16816(float* c, const uint32_t* a, const uint32_t* b) {
    asm volatile("mma.sync.aligned.m16n8k16.row.col.f32.f16.f16.f32 "
                 "{%0,%1,%2,%3}, {%4,%5,%6,%7}, {%8,%9}, {%0,%1,%2,%3};"
                 : "+f"(c[0]), "+f"(c[1]), "+f"(c[2]), "+f"(c[3])
                 : "r"(a[0]), "r"(a[1]), "r"(a[2]), "r"(a[3]), "r"(b[0]), "r"(b[1]));
}

#define CPA16(dst, src, n) \
    asm volatile("cp.async.cg.shared.global [%0], [%1], 16, %2;" \
                 :: "r"(dst), "l"(src), "r"(n))

// 2-stage double buffer; each stage holds A / Bhi / Blo tiles of 128x16 fp16
// (row pitch 48B -> conflict-free ldmatrix phases). Stage stride 18432 B.
#define TILE_B    6144
#define STAGE_B   18432
#define GEMM_SMEM (STAGE_B * 2)

__global__ __launch_bounds__(256) void mma_gemm_kernel(const float* __restrict__ a_src,
                                                       const float* __restrict__ a_dst,
                                                       int layer) {
    extern __shared__ char smem[];
    uint32_t sb;
    asm("{ .reg .u64 t; cvta.to.shared.u64 t, %1; cvt.u32.u64 %0, t; }"
        : "=r"(sb) : "l"(smem));

    const int tid = threadIdx.x, lane = tid & 31, wid = tid >> 5;
    const int warpM = wid & 3, warpN = wid >> 2;
    const int bm = blockIdx.y, bn = blockIdx.x;

    // staging: thread -> one 16B chunk per tile per stage
    const int srow = tid >> 1, shalf = tid & 1;
    const uint32_t sdst = (uint32_t)(srow * 48 + shalf * 16);
    int grA = bm * 128 + srow;
    const uint32_t aok = (grA < NNODES) ? 16u : 0u;
    if (grA >= NNODES) grA = 0;   // keep address in-bounds; src-size=0 zero-fills
    const char* pA  = (const char*)(g_in + (size_t)grA * DIM + shalf * 8);
    const char* pBh = (const char*)(&g_wt_hi[layer][(size_t)(bn * 128 + srow) * DIM] + shalf * 8);
    const char* pBl = (const char*)(&g_wt_lo[layer][(size_t)(bn * 128 + srow) * DIM] + shalf * 8);

    float c[2][8][4];
#pragma unroll
    for (int i = 0; i < 2; i++)
#pragma unroll
        for (int j = 0; j < 8; j++)
#pragma unroll
            for (int q = 0; q < 4; q++) c[i][j][q] = 0.0f;

#define ISSUE(S, KB)                                                       \
    do {                                                                   \
        uint32_t st = sb + (S) * STAGE_B + sdst;                           \
        CPA16(st + 0 * TILE_B, pA  + (KB), aok);                           \
        CPA16(st + 1 * TILE_B, pBh + (KB), 16u);                           \
        CPA16(st + 2 * TILE_B, pBl + (KB), 16u);                           \
        asm volatile("cp.async.commit_group;" ::: "memory");               \
    } while (0)

    const uint32_t aoff = (uint32_t)((warpM * 32 + (lane & 15)) * 48 + ((lane >> 4) << 4));
    const uint32_t boff = (uint32_t)((warpN * 64 + ((lane >> 4) & 1) * 8 + (lane & 7)) * 48 +
                                     (((lane >> 3) & 1) << 4));

    ISSUE(0, 0);

    int buf = 0;
    for (int kc = 0; kc < 16; kc++) {
        asm volatile("cp.async.wait_group 0;" ::: "memory");  // stage kc landed
        __syncthreads();   // visibility + all reads of buf^1 (iter kc-1) finished
        if (kc < 15) ISSUE(buf ^ 1, (kc + 1) * 32);           // overlaps compute below

        const uint32_t stg = sb + buf * STAGE_B;
        uint32_t ah[2][4], bh[8][2], blr[8][2];
        ldsm4(ah[0], stg + 0 * TILE_B + aoff);
        ldsm4(ah[1], stg + 0 * TILE_B + aoff + 16 * 48);
#pragma unroll
        for (int p = 0; p < 4; p++) {
            ldsm4(&bh[2 * p][0], stg + 1 * TILE_B + boff + p * 16 * 48);
            ldsm4(&blr[2 * p][0], stg + 2 * TILE_B + boff + p * 16 * 48);
        }

#pragma unroll
        for (int tm = 0; tm < 2; tm++)
#pragma unroll
            for (int tn = 0; tn < 8; tn++) {
                mma16816(c[tm][tn], ah[tm], bh[tn]);   // A * B_hi
                mma16816(c[tm][tn], ah[tm], blr[tn]);  // A * B_lo
            }
        buf ^= 1;
    }

    // ---- epilogue: fp16 store + fused per-head logit partials ----
    // head h occupies cols [h*32, h*32+32) -> entirely inside this (bn, warpN)
    // 64-col group: head = bn*4 + warpN*2 + (tn>>2). Each thread covers 16 cols
    // of 4 rows; reduce partials over the 4 lanes sharing a row (lane&3).
    const int g = lane >> 2, cc = (lane & 3) * 2;
    float ps[2][2][2], pd[2][2][2];   // [tm][rowhalf][hh]
#pragma unroll
    for (int tm = 0; tm < 2; tm++)
#pragma unroll
        for (int rh = 0; rh < 2; rh++)
#pragma unroll
            for (int hh = 0; hh < 2; hh++) { ps[tm][rh][hh] = 0.f; pd[tm][rh][hh] = 0.f; }

#pragma unroll
    for (int tm = 0; tm < 2; tm++) {
        int r0 = bm * 128 + warpM * 32 + tm * 16 + g;
        int r1 = r0 + 8;
#pragma unroll
        for (int tn = 0; tn < 8; tn++) {
            int col = bn * 128 + warpN * 64 + tn * 8 + cc;
            float2 av = *(const float2*)&a_src[col];
            float2 dv = *(const float2*)&a_dst[col];
            int hh = tn >> 2;
            ps[tm][0][hh] += c[tm][tn][0] * av.x + c[tm][tn][1] * av.y;
            pd[tm][0][hh] += c[tm][tn][0] * dv.x + c[tm][tn][1] * dv.y;
            ps[tm][1][hh] += c[tm][tn][2] * av.x + c[tm][tn][3] * av.y;
            pd[tm][1][hh] += c[tm][tn][2] * dv.x + c[tm][tn][3] * dv.y;
            if (r0 < NNODES)
                *(__half2*)&g_xh16[(size_t)r0 * DIM + col] =
                    __floats2half2_rn(c[tm][tn][0], c[tm][tn][1]);
            if (r1 < NNODES)
                *(__half2*)&g_xh16[(size_t)r1 * DIM + col] =
                    __floats2half2_rn(c[tm][tn][2], c[tm][tn][3]);
        }
    }

    // reduce over the 4 lanes that share each row (lane&3 = 0..3)
#pragma unroll
    for (int tm = 0; tm < 2; tm++)
#pragma unroll
        for (int rh = 0; rh < 2; rh++)
#pragma unroll
            for (int hh = 0; hh < 2; hh++) {
                float vs = ps[tm][rh][hh], vd = pd[tm][rh][hh];
                vs += __shfl_xor_sync(0xffffffffu, vs, 1);
                vs += __shfl_xor_sync(0xffffffffu, vs, 2);
                vd += __shfl_xor_sync(0xffffffffu, vd, 1);
                vd += __shfl_xor_sync(0xffffffffu, vd, 2);
                ps[tm][rh][hh] = vs;
                pd[tm][rh][hh] = vd;
            }

    if ((lane & 3) == 0) {
        int headbase = bn * 4 + warpN * 2;
#pragma unroll
        for (int tm = 0; tm < 2; tm++)
#pragma unroll
            for (int rh = 0; rh < 2; rh++) {
                int r = bm * 128 + warpM * 32 + tm * 16 + g + rh * 8;
                if (r < NNODES) {
#pragma unroll
                    for (int hh = 0; hh < 2; hh++) {
                        g_als[r * HEADS + headbase + hh] = ps[tm][rh][hh];
                        g_ald[r * HEADS + headbase + hh] = pd[tm][rh][hh];
                    }
                }
            }
    }
#undef ISSUE
}

// ---------------- fused online-softmax aggregation (CSR), 2-edge unrolled --------
// one warp per dst node; lane l handles channels [8l,8l+8), head = l>>2
// gathers fp16 mirror; layers 0-2 write ELU(out) as fp16 (next GEMM A operand)
// 128-thread blocks: finer retirement granularity vs per-node degree variance
__global__ __launch_bounds__(128) void aggr_fused_kernel(const float* __restrict__ bvec,
                                                         float* __restrict__ out,
                                                         int apply_elu) {
    int warp = (blockIdx.x * blockDim.x + threadIdx.x) >> 5;
    int lane = threadIdx.x & 31;
    if (warp >= NNODES) return;

    int beg = g_off[warp], end = g_off[warp + 1];
    int h = lane >> 2;
    float aldh = g_ald[warp * HEADS + h];

    float m = -INFINITY, denom = 0.0f;
    float acc[8];
#pragma unroll
    for (int j = 0; j < 8; j++) acc[j] = 0.0f;

    int i = beg;
    for (; i + 2 <= end; i += 2) {
        int s0 = g_csr_src[i];
        int s1 = g_csr_src[i + 1];
        // issue both gathers + both logit loads before any dependent math (MLP=2)
        uint4 raw0 = *(const uint4*)(g_xh16 + (size_t)s0 * DIM + lane * 8);
        uint4 raw1 = *(const uint4*)(g_xh16 + (size_t)s1 * DIM + lane * 8);
        float e0 = g_als[s0 * HEADS + h];
        float e1 = g_als[s1 * HEADS + h];

        e0 += aldh; e0 = e0 > 0.0f ? e0 : 0.2f * e0;
        e1 += aldh; e1 = e1 > 0.0f ? e1 : 0.2f * e1;

        float mn = fmaxf(m, fmaxf(e0, e1));
        float r  = __expf(m - mn);          // m=-inf first time -> r=0
        float a0 = __expf(e0 - mn);
        float a1 = __expf(e1 - mn);
        denom = denom * r + a0 + a1;
        m = mn;

        float2 u0 = __half22float2(*(__half2*)&raw0.x);
        float2 u1 = __half22float2(*(__half2*)&raw0.y);
        float2 u2 = __half22float2(*(__half2*)&raw0.z);
        float2 u3 = __half22float2(*(__half2*)&raw0.w);
        float2 w0 = __half22float2(*(__half2*)&raw1.x);
        float2 w1 = __half22float2(*(__half2*)&raw1.y);
        float2 w2 = __half22float2(*(__half2*)&raw1.z);
        float2 w3 = __half22float2(*(__half2*)&raw1.w);

        acc[0] = acc[0] * r + a0 * u0.x + a1 * w0.x;
        acc[1] = acc[1] * r + a0 * u0.y + a1 * w0.y;
        acc[2] = acc[2] * r + a0 * u1.x + a1 * w1.x;
        acc[3] = acc[3] * r + a0 * u1.y + a1 * w1.y;
        acc[4] = acc[4] * r + a0 * u2.x + a1 * w2.x;
        acc[5] = acc[5] * r + a0 * u2.y + a1 * w2.y;
        acc[6] = acc[6] * r + a0 * u3.x + a1 * w3.x;
        acc[7] = acc[7] * r + a0 * u3.y + a1 * w3.y;
    }
    if (i < end) {
        int s = g_csr_src[i];
        uint4 raw = *(const uint4*)(g_xh16 + (size_t)s * DIM + lane * 8);
        float e = g_als[s * HEADS + h] + aldh;
        e = e > 0.0f ? e : 0.2f * e;
        float mn = fmaxf(m, e);
        float r = __expf(m - mn);
        float a = __expf(e - mn);
        denom = denom * r + a;
        m = mn;
        float2 u0 = __half22float2(*(__half2*)&raw.x);
        float2 u1 = __half22float2(*(__half2*)&raw.y);
        float2 u2 = __half22float2(*(__half2*)&raw.z);
        float2 u3 = __half22float2(*(__half2*)&raw.w);
        acc[0] = acc[0] * r + a * u0.x;
        acc[1] = acc[1] * r + a * u0.y;
        acc[2] = acc[2] * r + a * u1.x;
        acc[3] = acc[3] * r + a * u1.y;
        acc[4] = acc[4] * r + a * u2.x;
        acc[5] = acc[5] * r + a * u2.y;
        acc[6] = acc[6] * r + a * u3.x;
        acc[7] = acc[7] * r + a * u3.y;
    }

    float inv = 1.0f / denom;
    const float* bb = bvec + lane * 8;
    float v[8];
#pragma unroll
    for (int j = 0; j < 8; j++) v[j] = acc[j] * inv + bb[j];

    if (apply_elu) {
        __half2 o2[4];
#pragma unroll
        for (int j = 0; j < 8; j += 2) {
            float v0 = v[j] > 0.0f ? v[j] : expm1f(v[j]);
            float v1 = v[j + 1] > 0.0f ? v[j + 1] : expm1f(v[j + 1]);
            o2[j >> 1] = __floats2half2_rn(v0, v1);
        }
        *(uint4*)(g_in + (size_t)warp * DIM + lane * 8) = *(uint4*)o2;
    } else {
        float* o = out + (size_t)warp * DIM + lane * 8;
        *(float4*)(o + 0) = make_float4(v[0], v[1], v[2], v[3]);
        *(float4*)(o + 4) = make_float4(v[4], v[5], v[6], v[7]);
    }
}

// ---------------- host launcher ----------------
extern "C" void kernel_launch(void* const* d_in, const int* in_sizes, int n_in,
                              void* d_out, int out_size) {
    const float* x  = (const float*)d_in[0];
    const int*   ei = (const int*)d_in[1];
    float* out = (float*)d_out;

    cudaFuncSetAttribute(mma_gemm_kernel,
                         cudaFuncAttributeMaxDynamicSharedMemorySize, GEMM_SMEM);

    const int TPB = 256;
    dim3 gemm_grid(DIM / 128, (NNODES + 127) / 128);
    int node_blocks = (NNODES + TPB - 1) / TPB;
    int edge_blocks = (ETOT + TPB - 1) / TPB;
    int aggr_blocks = (NNODES * 32 + 127) / 128;     // 128-thread blocks
    int wsplit_blocks = (4 * DIM * DIM) / TPB;
    int xsplit_blocks = (NNODES * DIM / 4 + TPB - 1) / TPB;

    // ---- fork: CSR build (side stream) overlaps splits + layer-0 GEMM (main) ----
    // CSR is only needed by the layer-0 aggregation; fork/join with events is the
    // documented capture-legal pattern. Stream/events are host objects (no device
    // allocation); not destroyed since they remain referenced by the capture.
    cudaStream_t s1;
    cudaStreamCreateWithFlags(&s1, cudaStreamNonBlocking);
    cudaEvent_t evFork, evJoin;
    cudaEventCreateWithFlags(&evFork, cudaEventDisableTiming);
    cudaEventCreateWithFlags(&evJoin, cudaEventDisableTiming);

    cudaEventRecord(evFork, 0);
    cudaStreamWaitEvent(s1, evFork, 0);

    csr_zero_kernel<<<node_blocks, TPB, 0, s1>>>();
    csr_count_kernel<<<edge_blocks, TPB, 0, s1>>>(ei);
    csr_scan_kernel<<<1, 1024, 0, s1>>>();
    csr_scatter_kernel<<<edge_blocks, TPB, 0, s1>>>(ei);
    cudaEventRecord(evJoin, s1);

    // main stream: weight/input splits + layer-0 GEMM run concurrently with CSR
    wsplit_all_kernel<<<wsplit_blocks, TPB>>>((const float*)d_in[2], (const float*)d_in[6],
                                              (const float*)d_in[10], (const float*)d_in[14]);
    xsplit_kernel<<<xsplit_blocks, TPB>>>(x);

    for (int layer = 0; layer < 4; layer++) {
        const float* as_ = (const float*)d_in[3 + 4 * layer];
        const float* ad_ = (const float*)d_in[4 + 4 * layer];
        const float* b   = (const float*)d_in[5 + 4 * layer];

        mma_gemm_kernel<<<gemm_grid, TPB, GEMM_SMEM>>>(as_, ad_, layer);
        if (layer == 0) cudaStreamWaitEvent(0, evJoin, 0);   // join: aggr needs CSR
        aggr_fused_kernel<<<aggr_blocks, 128>>>(b, (layer < 3) ? nullptr : out,
                                                layer < 3 ? 1 : 0);
    }
}